// round 14
// baseline (speedup 1.0000x reference)
#include <cuda_runtime.h>
#include <cuda_fp16.h>
#include <math.h>
#include <stdint.h>

// ---------------------------------------------------------------------------
// RankingCNN: conv(s32,k32) == GEMM C[3072,1568] = Wb[3072,3072] @ P[3072,1568]
// R14: mlp1 restructured — pooled transposed to [branch][1024][32] so lane=image:
// coalesced pooled loads, broadcast weight loads, NO shuffle reductions.
// (ncu showed mlp1 latency-bound: occ 16%, issue 4.5%, 32 serial reductions/warp)
// ---------------------------------------------------------------------------

#define NBR 3
#define BATCH 32
#define KDIM 3072
#define MDIM 3072
#define NDIM 1568
#define NPAD 1664            // 13 * 128; pad rows stay zero (static init)
#define RANK_OFF 0
#define CAM_OFF 96
#define FEAT_OFF 9504
#define FPB 1605632
#define FPI 50176

#define BM 64
#define BN 128
#define BK 32
#define NC (KDIM / BK)       // 96 k-chunks

#define A_T 4096             // A tile (64 x 64B)
#define STAGE_B 12288        // Ah | Bh
#define NSTAGE 4
#define SMEM_DYN (NSTAGE * STAGE_B)   // 49152

// ---- static scratch (no allocations allowed) ------------------------------
__device__ __align__(256) __half g_Ah[MDIM * KDIM];
__device__ __align__(256) __half g_Bh[NPAD * KDIM];   // pad rows never written -> 0
__device__ float g_pooled[NBR * 1024 * BATCH];        // [branch][channel][image]
__device__ float g_h[NBR * BATCH * 512];
__device__ float g_camp[8 * NBR * 2 * NDIM];          // per-chunk CAM partials

// ---- PTX helpers ----------------------------------------------------------
__device__ __forceinline__ uint32_t smem_u32(const void* p) {
    uint32_t a;
    asm("{ .reg .u64 t; cvta.to.shared.u64 t, %1; cvt.u32.u64 %0, t; }" : "=r"(a) : "l"(p));
    return a;
}
__device__ __forceinline__ void cp16(uint32_t dst, const void* src) {
    asm volatile("cp.async.cg.shared.global [%0], [%1], 16;" :: "r"(dst), "l"(src));
}
__device__ __forceinline__ void ldmx4(uint32_t* r, uint32_t a) {
    asm volatile("ldmatrix.sync.aligned.m8n8.x4.shared.b16 {%0,%1,%2,%3}, [%4];"
        : "=r"(r[0]), "=r"(r[1]), "=r"(r[2]), "=r"(r[3]) : "r"(a));
}
__device__ __forceinline__ void mma16816(float* c, const uint32_t* a, const uint32_t* b) {
    asm volatile("mma.sync.aligned.m16n8k16.row.col.f32.f16.f16.f32 "
        "{%0,%1,%2,%3}, {%4,%5,%6,%7}, {%8,%9}, {%0,%1,%2,%3};"
        : "+f"(c[0]), "+f"(c[1]), "+f"(c[2]), "+f"(c[3])
        : "r"(a[0]), "r"(a[1]), "r"(a[2]), "r"(a[3]), "r"(b[0]), "r"(b[1]));
}
__device__ __forceinline__ uint2 cvt4(float4 v) {
    __half2 lo = __floats2half2_rn(v.x, v.y);
    __half2 hi = __floats2half2_rn(v.z, v.w);
    uint2 o;
    o.x = *(uint32_t*)&lo;
    o.y = *(uint32_t*)&hi;
    return o;
}

// ---------------------------------------------------------------------------
// Kernel 1: fused prep, float4 per thread.
// ---------------------------------------------------------------------------
#define A4_BLKS 9216         // (3072*3072/4) / 256
#define B4_BLKS 4704         // (1568*3072/4) / 256

__global__ __launch_bounds__(256) void prep_kernel(const float* __restrict__ Wb,
                                                   const float* __restrict__ x) {
    if (blockIdx.x < A4_BLKS) {
        int i4 = (blockIdx.x * 256 + threadIdx.x) * 4;
        float4 v = *(const float4*)(Wb + i4);
        *(uint2*)(g_Ah + i4) = cvt4(v);
    } else {
        int i4 = ((blockIdx.x - A4_BLKS) * 256 + threadIdx.x) * 4;
        int n = i4 / KDIM;
        int k = i4 - n * KDIM;          // multiple of 4 -> kw multiple of 4
        int c = k >> 10, r = k & 1023, kh = r >> 5, kw = r & 31;
        int b = n / 49, t = n - b * 49, ii = t / 7, jj = t - ii * 7;
        const float* src = x + ((size_t)(b * 3 + c) * 224 + ii * 32 + kh) * 224 + jj * 32 + kw;
        float4 v = *(const float4*)src;
        *(uint2*)(g_Bh + i4) = cvt4(v);
    }
}

// ---------------------------------------------------------------------------
// Kernel 2: GEMM 64x128x32 per CTA, 4 warps of 64x32 (1m x 4n), 4 stages.
// ---------------------------------------------------------------------------
__global__ __launch_bounds__(128, 3) void gemm_mma_kernel(const float* __restrict__ bias,
                                                          float* __restrict__ out) {
    extern __shared__ char smem[];
    const uint32_t s0 = smem_u32(smem);

    const int tid = threadIdx.x;
    const int wid = tid >> 5;
    const int lane = tid & 31;
    const int mBase = blockIdx.y * BM;
    const int nBase = blockIdx.x * BN;

    const int c = tid & 3;
    const int r = tid >> 2;                     // 0..31
    const uint32_t cSw = (uint32_t)((c ^ ((r >> 1) & 3)) << 4);
    const uint32_t rOff = (uint32_t)(r * 64) + cSw;
    const __half* gAh = g_Ah + (size_t)(mBase + r) * KDIM + c * 8;
    const __half* gBh = g_Bh + (size_t)(nBase + r) * KDIM + c * 8;
    const size_t j32 = (size_t)32 * KDIM;

#define ISSUE(kt) do {                                                          \
        const uint32_t st = s0 + (uint32_t)(((kt) & 3) * STAGE_B);              \
        const int k0 = (kt) * BK;                                               \
        cp16(st + rOff,               gAh + k0);                                \
        cp16(st + rOff + 2048,        gAh + j32 + k0);                          \
        cp16(st + A_T + rOff,         gBh + k0);                                \
        cp16(st + A_T + rOff + 2048,  gBh + j32 + k0);                          \
        cp16(st + A_T + rOff + 4096,  gBh + 2*j32 + k0);                        \
        cp16(st + A_T + rOff + 6144,  gBh + 3*j32 + k0);                        \
        asm volatile("cp.async.commit_group;");                                 \
    } while (0)

    float acc[4][4][4];
#pragma unroll
    for (int i = 0; i < 4; i++)
#pragma unroll
        for (int j = 0; j < 4; j++)
#pragma unroll
            for (int q = 0; q < 4; q++) acc[i][j][q] = 0.f;

    const int aR = lane & 15;
    const int aHi = lane >> 4;
    const int bR = wid * 32 + ((lane >> 4) << 3) + (lane & 7);
    const int bHi = (lane >> 3) & 1;

    ISSUE(0); ISSUE(1); ISSUE(2);

    for (int kt = 0; kt < NC; kt++) {
        asm volatile("cp.async.wait_group 2;");
        __syncthreads();
        if (kt + 3 < NC) ISSUE(kt + 3);
        else asm volatile("cp.async.commit_group;");

        const uint32_t sb = s0 + (uint32_t)((kt & 3) * STAGE_B);

        uint32_t ah[2][4][4], bh[2][4][2];
#pragma unroll
        for (int ks = 0; ks < 2; ks++) {
#pragma unroll
            for (int mf = 0; mf < 4; mf++) {
                const int row = aR + mf * 16;
                const uint32_t ad = sb + (uint32_t)(row * 64)
                    + (uint32_t)(((ks * 2 + aHi) ^ ((row >> 1) & 3)) << 4);
                ldmx4(ah[ks][mf], ad);
            }
#pragma unroll
            for (int p = 0; p < 2; p++) {
                const int row = bR + p * 16;
                const uint32_t bd = sb + A_T + (uint32_t)(row * 64)
                    + (uint32_t)(((ks * 2 + bHi) ^ ((row >> 1) & 3)) << 4);
                uint32_t t[4];
                ldmx4(t, bd);
                bh[ks][2*p][0] = t[0]; bh[ks][2*p][1] = t[1];
                bh[ks][2*p+1][0] = t[2]; bh[ks][2*p+1][1] = t[3];
            }
        }

#pragma unroll
        for (int ks = 0; ks < 2; ks++)
#pragma unroll
            for (int mf = 0; mf < 4; mf++)
#pragma unroll
                for (int nf = 0; nf < 4; nf++)
                    mma16816(acc[mf][nf], ah[ks][mf], bh[ks][nf]);
    }

#pragma unroll
    for (int mf = 0; mf < 4; mf++) {
        const int m0 = mBase + mf * 16 + (lane >> 2);
        const int m1 = m0 + 8;
        const float bv0 = bias[m0], bv1 = bias[m1];
        float* ob0 = out + FEAT_OFF + (size_t)(m0 >> 10) * FPB + (size_t)(m0 & 1023) * 49;
        float* ob1 = out + FEAT_OFF + (size_t)(m1 >> 10) * FPB + (size_t)(m1 & 1023) * 49;
#pragma unroll
        for (int nf = 0; nf < 4; nf++) {
            const int n = nBase + wid * 32 + nf * 8 + (lane & 3) * 2;
            if (n < NDIM) {
                int b0 = n / 49,       sA = n - b0 * 49;
                int b1 = (n + 1) / 49, sB = (n + 1) - b1 * 49;
                ob0[(size_t)b0 * FPI + sA] = acc[mf][nf][0] + bv0;
                ob0[(size_t)b1 * FPI + sB] = acc[mf][nf][1] + bv0;
                ob1[(size_t)b0 * FPI + sA] = acc[mf][nf][2] + bv1;
                ob1[(size_t)b1 * FPI + sB] = acc[mf][nf][3] + bv1;
            }
        }
    }
#undef ISSUE
}

// ---------------------------------------------------------------------------
// Kernel 3: postproc — grid (96, 8): one block per (branch,image,chunk).
// GAP writes TRANSPOSED pooled: [branch][channel][image].
// ---------------------------------------------------------------------------
__global__ __launch_bounds__(256) void postproc_kernel(const float* __restrict__ out_r,
                                                       const float* __restrict__ clsw) {
    __shared__ float tile[128 * 49];
    __shared__ float wsh[256];
    const int n = blockIdx.x >> 5, b = blockIdx.x & 31;
    const int ch = blockIdx.y;
    const int tid = threadIdx.x, w = tid >> 5, lane = tid & 31;
    const float* f = out_r + FEAT_OFF + (size_t)n * FPB + (size_t)b * FPI + ch * (128 * 49);

    if (tid < 256) {
        int cls = tid >> 7, j = tid & 127;
        wsh[tid] = clsw[n * 2048 + cls * 1024 + ch * 128 + j];
    }
    {
        const float4* f4 = (const float4*)f;
        float4* t4 = (float4*)tile;
        for (int i = tid; i < 1568; i += 256) t4[i] = f4[i];
    }
    __syncthreads();

    if (tid < 128) {
        float s = 0.f;
        const float* tp = tile + tid * 49;
#pragma unroll
        for (int q = 0; q < 49; q++) s += tp[q];
        g_pooled[(n * 1024 + ch * 128 + tid) * 32 + b] = s * (1.0f / 49.0f);
    }

    const int nd = (w < 2) ? 13 : 12;
#pragma unroll
    for (int di = 0; di < 13; di++) {
        if (di >= nd) break;
        int d = w + di * 8;
        int cls = d / 49, s = d - cls * 49;
        const float* wp = wsh + cls * 128;
        float a = 0.f;
#pragma unroll
        for (int o4 = 0; o4 < 4; o4++)
            a = fmaf(wp[o4 * 32 + lane], tile[(o4 * 32 + lane) * 49 + s], a);
#pragma unroll
        for (int off = 16; off; off >>= 1) a += __shfl_xor_sync(0xffffffffu, a, off);
        if (lane == 0)
            g_camp[ch * (NBR * 2 * NDIM) + (n * 2 + cls) * NDIM + b * 49 + s] = a;
    }
}

// ---------------------------------------------------------------------------
// Kernel 4: mlp1 — lane = image. Warp owns 2 output channels (j0, j1).
// Per t: coalesced pooled load + float4-broadcast weights, no reductions.
// grid (32, NBR), 256 threads = 8 warps -> 16 j per block. + CAM finalize.
// ---------------------------------------------------------------------------
__global__ __launch_bounds__(256) void mlp1_kernel(const float* __restrict__ p1w,
                                                   const float* __restrict__ p1b,
                                                   float* __restrict__ out) {
    const int branch = blockIdx.y;
    const int tid = threadIdx.x;
    const int wid = tid >> 5, lane = tid & 31;

    // ---- CAM finalize: 96 blocks x 98 values covers 3*2*1568 ---------------
    if (tid < 98) {
        int idx = branch * (2 * NDIM) + blockIdx.x * 98 + tid;
        float s = 0.f;
#pragma unroll
        for (int ch = 0; ch < 8; ch++) s += g_camp[ch * (NBR * 2 * NDIM) + idx];
        out[CAM_OFF + idx] = fmaxf(s, 0.f);
    }

    // ---- Linear(1024,512)+ReLU: lane=image, warp=(j0,j1) -------------------
    const int j0 = blockIdx.x * 16 + wid * 2;
    const float* w0p = p1w + (size_t)(branch * 512 + j0) * 1024;
    const float* w1p = w0p + 1024;
    const float* pp = g_pooled + branch * 1024 * 32 + lane;

    float a0 = 0.f, a1 = 0.f, a2 = 0.f, a3 = 0.f;   // (j0,j1) x 2-way ILP
    for (int t = 0; t < 1024; t += 4) {
        float4 w0 = *(const float4*)(w0p + t);
        float4 w1 = *(const float4*)(w1p + t);
        float p0 = pp[(t + 0) * 32];
        float p1 = pp[(t + 1) * 32];
        float p2 = pp[(t + 2) * 32];
        float p3 = pp[(t + 3) * 32];
        a0 = fmaf(w0.x, p0, a0); a2 = fmaf(w0.y, p1, a2);
        a0 = fmaf(w0.z, p2, a0); a2 = fmaf(w0.w, p3, a2);
        a1 = fmaf(w1.x, p0, a1); a3 = fmaf(w1.y, p1, a3);
        a1 = fmaf(w1.z, p2, a1); a3 = fmaf(w1.w, p3, a3);
    }
    const float b0 = p1b[branch * 512 + j0];
    const float b1 = p1b[branch * 512 + j0 + 1];
    float* hb = g_h + (branch * 32 + lane) * 512;
    hb[j0]     = fmaxf(a0 + a2 + b0, 0.f);
    hb[j0 + 1] = fmaxf(a1 + a3 + b1, 0.f);
}

// ---------------------------------------------------------------------------
// Kernel 5: Linear(512,2) + softmax[:,1] — grid 96 (one block per branch,image)
// ---------------------------------------------------------------------------
__global__ __launch_bounds__(64) void mlp2_kernel(const float* __restrict__ p2w,
                                                  const float* __restrict__ p2b,
                                                  float* __restrict__ out) {
    const int branch = blockIdx.x / 32, b = blockIdx.x & 31;
    const int wid = threadIdx.x >> 5, lane = threadIdx.x & 31;
    const float* wv = p2w + branch * 1024 + wid * 512;
    const float* h = g_h + (branch * 32 + b) * 512;
    float s = 0.f;
#pragma unroll
    for (int t = 0; t < 16; t++) s = fmaf(h[t * 32 + lane], wv[t * 32 + lane], s);
#pragma unroll
    for (int off = 16; off; off >>= 1) s += __shfl_xor_sync(0xffffffffu, s, off);
    __shared__ float logit[2];
    if (lane == 0) logit[wid] = s + p2b[branch * 2 + wid];
    __syncthreads();
    if (threadIdx.x == 0) {
        float l0 = logit[0], l1 = logit[1];
        float mx = fmaxf(l0, l1);
        float e0 = expf(l0 - mx), e1 = expf(l1 - mx);
        out[RANK_OFF + b * 3 + branch] = e1 / (e0 + e1);
    }
}

// ---------------------------------------------------------------------------
// Launch: prep(1), gemm(2), postproc(3), mlp1(4 <- ncu slot), mlp2(5)
// ---------------------------------------------------------------------------
extern "C" void kernel_launch(void* const* d_in, const int* in_sizes, int n_in,
                              void* d_out, int out_size) {
    const float* x    = (const float*)d_in[0];
    const float* Wb   = (const float*)d_in[1];
    const float* bb   = (const float*)d_in[2];
    const float* p1w  = (const float*)d_in[3];
    const float* p1b  = (const float*)d_in[4];
    const float* p2w  = (const float*)d_in[5];
    const float* p2b  = (const float*)d_in[6];
    const float* clsw = (const float*)d_in[7];
    float* out = (float*)d_out;

    prep_kernel<<<A4_BLKS + B4_BLKS, 256>>>(Wb, x);

    cudaFuncSetAttribute(gemm_mma_kernel, cudaFuncAttributeMaxDynamicSharedMemorySize, SMEM_DYN);
    dim3 ggrid(NPAD / BN, MDIM / BM);   // (13, 48)
    gemm_mma_kernel<<<ggrid, 128, SMEM_DYN>>>(bb, out);

    postproc_kernel<<<dim3(NBR * BATCH, 8), 256>>>(out, clsw);
    mlp1_kernel<<<dim3(32, NBR), 256>>>(p1w, p1b, out);
    mlp2_kernel<<<NBR * BATCH, 64>>>(p2w, p2b, out);
}

// round 15
// speedup vs baseline: 1.3056x; 1.3056x over previous
#include <cuda_runtime.h>
#include <cuda_fp16.h>
#include <math.h>
#include <stdint.h>

// ---------------------------------------------------------------------------
// RankingCNN: conv(s32,k32) == GEMM C[3072,1568] = Wb[3072,3072] @ P[3072,1568]
// R15: mlp1 redone with split-k: grid (64,3,2)=384 blocks, warp=one j,
// lane=image (coalesced pooled, broadcast weights, no reductions), unroll-8
// for ~10 outstanding loads/warp. Partials -> g_hp[2]; mlp2 fuses add+bias+relu.
// (R14 failed: 96 blocks = 0.65 waves + low MLP -> latency-bound, issue 4.2%)
// ---------------------------------------------------------------------------

#define NBR 3
#define BATCH 32
#define KDIM 3072
#define MDIM 3072
#define NDIM 1568
#define NPAD 1664            // 13 * 128; pad rows stay zero (static init)
#define RANK_OFF 0
#define CAM_OFF 96
#define FEAT_OFF 9504
#define FPB 1605632
#define FPI 50176

#define BM 64
#define BN 128
#define BK 32
#define NC (KDIM / BK)       // 96 k-chunks

#define A_T 4096             // A tile (64 x 64B)
#define STAGE_B 12288        // Ah | Bh
#define NSTAGE 4
#define SMEM_DYN (NSTAGE * STAGE_B)   // 49152

// ---- static scratch (no allocations allowed) ------------------------------
__device__ __align__(256) __half g_Ah[MDIM * KDIM];
__device__ __align__(256) __half g_Bh[NPAD * KDIM];   // pad rows never written -> 0
__device__ float g_pooled[NBR * 1024 * BATCH];        // [branch][channel][image]
__device__ float g_hp[2][NBR * BATCH * 512];          // split-k partials (no bias/relu)
__device__ float g_camp[8 * NBR * 2 * NDIM];          // per-chunk CAM partials

// ---- PTX helpers ----------------------------------------------------------
__device__ __forceinline__ uint32_t smem_u32(const void* p) {
    uint32_t a;
    asm("{ .reg .u64 t; cvta.to.shared.u64 t, %1; cvt.u32.u64 %0, t; }" : "=r"(a) : "l"(p));
    return a;
}
__device__ __forceinline__ void cp16(uint32_t dst, const void* src) {
    asm volatile("cp.async.cg.shared.global [%0], [%1], 16;" :: "r"(dst), "l"(src));
}
__device__ __forceinline__ void ldmx4(uint32_t* r, uint32_t a) {
    asm volatile("ldmatrix.sync.aligned.m8n8.x4.shared.b16 {%0,%1,%2,%3}, [%4];"
        : "=r"(r[0]), "=r"(r[1]), "=r"(r[2]), "=r"(r[3]) : "r"(a));
}
__device__ __forceinline__ void mma16816(float* c, const uint32_t* a, const uint32_t* b) {
    asm volatile("mma.sync.aligned.m16n8k16.row.col.f32.f16.f16.f32 "
        "{%0,%1,%2,%3}, {%4,%5,%6,%7}, {%8,%9}, {%0,%1,%2,%3};"
        : "+f"(c[0]), "+f"(c[1]), "+f"(c[2]), "+f"(c[3])
        : "r"(a[0]), "r"(a[1]), "r"(a[2]), "r"(a[3]), "r"(b[0]), "r"(b[1]));
}
__device__ __forceinline__ uint2 cvt4(float4 v) {
    __half2 lo = __floats2half2_rn(v.x, v.y);
    __half2 hi = __floats2half2_rn(v.z, v.w);
    uint2 o;
    o.x = *(uint32_t*)&lo;
    o.y = *(uint32_t*)&hi;
    return o;
}

// ---------------------------------------------------------------------------
// Kernel 1: fused prep, float4 per thread.
// ---------------------------------------------------------------------------
#define A4_BLKS 9216         // (3072*3072/4) / 256
#define B4_BLKS 4704         // (1568*3072/4) / 256

__global__ __launch_bounds__(256) void prep_kernel(const float* __restrict__ Wb,
                                                   const float* __restrict__ x) {
    if (blockIdx.x < A4_BLKS) {
        int i4 = (blockIdx.x * 256 + threadIdx.x) * 4;
        float4 v = *(const float4*)(Wb + i4);
        *(uint2*)(g_Ah + i4) = cvt4(v);
    } else {
        int i4 = ((blockIdx.x - A4_BLKS) * 256 + threadIdx.x) * 4;
        int n = i4 / KDIM;
        int k = i4 - n * KDIM;          // multiple of 4 -> kw multiple of 4
        int c = k >> 10, r = k & 1023, kh = r >> 5, kw = r & 31;
        int b = n / 49, t = n - b * 49, ii = t / 7, jj = t - ii * 7;
        const float* src = x + ((size_t)(b * 3 + c) * 224 + ii * 32 + kh) * 224 + jj * 32 + kw;
        float4 v = *(const float4*)src;
        *(uint2*)(g_Bh + i4) = cvt4(v);
    }
}

// ---------------------------------------------------------------------------
// Kernel 2: GEMM 64x128x32 per CTA, 4 warps of 64x32 (1m x 4n), 4 stages.
// ---------------------------------------------------------------------------
__global__ __launch_bounds__(128, 3) void gemm_mma_kernel(const float* __restrict__ bias,
                                                          float* __restrict__ out) {
    extern __shared__ char smem[];
    const uint32_t s0 = smem_u32(smem);

    const int tid = threadIdx.x;
    const int wid = tid >> 5;
    const int lane = tid & 31;
    const int mBase = blockIdx.y * BM;
    const int nBase = blockIdx.x * BN;

    const int c = tid & 3;
    const int r = tid >> 2;                     // 0..31
    const uint32_t cSw = (uint32_t)((c ^ ((r >> 1) & 3)) << 4);
    const uint32_t rOff = (uint32_t)(r * 64) + cSw;
    const __half* gAh = g_Ah + (size_t)(mBase + r) * KDIM + c * 8;
    const __half* gBh = g_Bh + (size_t)(nBase + r) * KDIM + c * 8;
    const size_t j32 = (size_t)32 * KDIM;

#define ISSUE(kt) do {                                                          \
        const uint32_t st = s0 + (uint32_t)(((kt) & 3) * STAGE_B);              \
        const int k0 = (kt) * BK;                                               \
        cp16(st + rOff,               gAh + k0);                                \
        cp16(st + rOff + 2048,        gAh + j32 + k0);                          \
        cp16(st + A_T + rOff,         gBh + k0);                                \
        cp16(st + A_T + rOff + 2048,  gBh + j32 + k0);                          \
        cp16(st + A_T + rOff + 4096,  gBh + 2*j32 + k0);                        \
        cp16(st + A_T + rOff + 6144,  gBh + 3*j32 + k0);                        \
        asm volatile("cp.async.commit_group;");                                 \
    } while (0)

    float acc[4][4][4];
#pragma unroll
    for (int i = 0; i < 4; i++)
#pragma unroll
        for (int j = 0; j < 4; j++)
#pragma unroll
            for (int q = 0; q < 4; q++) acc[i][j][q] = 0.f;

    const int aR = lane & 15;
    const int aHi = lane >> 4;
    const int bR = wid * 32 + ((lane >> 4) << 3) + (lane & 7);
    const int bHi = (lane >> 3) & 1;

    ISSUE(0); ISSUE(1); ISSUE(2);

    for (int kt = 0; kt < NC; kt++) {
        asm volatile("cp.async.wait_group 2;");
        __syncthreads();
        if (kt + 3 < NC) ISSUE(kt + 3);
        else asm volatile("cp.async.commit_group;");

        const uint32_t sb = s0 + (uint32_t)((kt & 3) * STAGE_B);

        uint32_t ah[2][4][4], bh[2][4][2];
#pragma unroll
        for (int ks = 0; ks < 2; ks++) {
#pragma unroll
            for (int mf = 0; mf < 4; mf++) {
                const int row = aR + mf * 16;
                const uint32_t ad = sb + (uint32_t)(row * 64)
                    + (uint32_t)(((ks * 2 + aHi) ^ ((row >> 1) & 3)) << 4);
                ldmx4(ah[ks][mf], ad);
            }
#pragma unroll
            for (int p = 0; p < 2; p++) {
                const int row = bR + p * 16;
                const uint32_t bd = sb + A_T + (uint32_t)(row * 64)
                    + (uint32_t)(((ks * 2 + bHi) ^ ((row >> 1) & 3)) << 4);
                uint32_t t[4];
                ldmx4(t, bd);
                bh[ks][2*p][0] = t[0]; bh[ks][2*p][1] = t[1];
                bh[ks][2*p+1][0] = t[2]; bh[ks][2*p+1][1] = t[3];
            }
        }

#pragma unroll
        for (int ks = 0; ks < 2; ks++)
#pragma unroll
            for (int mf = 0; mf < 4; mf++)
#pragma unroll
                for (int nf = 0; nf < 4; nf++)
                    mma16816(acc[mf][nf], ah[ks][mf], bh[ks][nf]);
    }

#pragma unroll
    for (int mf = 0; mf < 4; mf++) {
        const int m0 = mBase + mf * 16 + (lane >> 2);
        const int m1 = m0 + 8;
        const float bv0 = bias[m0], bv1 = bias[m1];
        float* ob0 = out + FEAT_OFF + (size_t)(m0 >> 10) * FPB + (size_t)(m0 & 1023) * 49;
        float* ob1 = out + FEAT_OFF + (size_t)(m1 >> 10) * FPB + (size_t)(m1 & 1023) * 49;
#pragma unroll
        for (int nf = 0; nf < 4; nf++) {
            const int n = nBase + wid * 32 + nf * 8 + (lane & 3) * 2;
            if (n < NDIM) {
                int b0 = n / 49,       sA = n - b0 * 49;
                int b1 = (n + 1) / 49, sB = (n + 1) - b1 * 49;
                ob0[(size_t)b0 * FPI + sA] = acc[mf][nf][0] + bv0;
                ob0[(size_t)b1 * FPI + sB] = acc[mf][nf][1] + bv0;
                ob1[(size_t)b0 * FPI + sA] = acc[mf][nf][2] + bv1;
                ob1[(size_t)b1 * FPI + sB] = acc[mf][nf][3] + bv1;
            }
        }
    }
#undef ISSUE
}

// ---------------------------------------------------------------------------
// Kernel 3: postproc — grid (96, 8): one block per (branch,image,chunk).
// GAP writes TRANSPOSED pooled: [branch][channel][image].
// ---------------------------------------------------------------------------
__global__ __launch_bounds__(256) void postproc_kernel(const float* __restrict__ out_r,
                                                       const float* __restrict__ clsw) {
    __shared__ float tile[128 * 49];
    __shared__ float wsh[256];
    const int n = blockIdx.x >> 5, b = blockIdx.x & 31;
    const int ch = blockIdx.y;
    const int tid = threadIdx.x, w = tid >> 5, lane = tid & 31;
    const float* f = out_r + FEAT_OFF + (size_t)n * FPB + (size_t)b * FPI + ch * (128 * 49);

    if (tid < 256) {
        int cls = tid >> 7, j = tid & 127;
        wsh[tid] = clsw[n * 2048 + cls * 1024 + ch * 128 + j];
    }
    {
        const float4* f4 = (const float4*)f;
        float4* t4 = (float4*)tile;
        for (int i = tid; i < 1568; i += 256) t4[i] = f4[i];
    }
    __syncthreads();

    if (tid < 128) {
        float s = 0.f;
        const float* tp = tile + tid * 49;
#pragma unroll
        for (int q = 0; q < 49; q++) s += tp[q];
        g_pooled[(n * 1024 + ch * 128 + tid) * 32 + b] = s * (1.0f / 49.0f);
    }

    const int nd = (w < 2) ? 13 : 12;
#pragma unroll
    for (int di = 0; di < 13; di++) {
        if (di >= nd) break;
        int d = w + di * 8;
        int cls = d / 49, s = d - cls * 49;
        const float* wp = wsh + cls * 128;
        float a = 0.f;
#pragma unroll
        for (int o4 = 0; o4 < 4; o4++)
            a = fmaf(wp[o4 * 32 + lane], tile[(o4 * 32 + lane) * 49 + s], a);
#pragma unroll
        for (int off = 16; off; off >>= 1) a += __shfl_xor_sync(0xffffffffu, a, off);
        if (lane == 0)
            g_camp[ch * (NBR * 2 * NDIM) + (n * 2 + cls) * NDIM + b * 49 + s] = a;
    }
}

// ---------------------------------------------------------------------------
// Kernel 4: mlp1 split-k — grid (64, NBR, 2). Warp = one j; lane = image;
// kz = blockIdx.z selects k-half. Partial dot -> g_hp[kz]. + CAM finalize (z=0).
// ---------------------------------------------------------------------------
__global__ __launch_bounds__(256) void mlp1_kernel(const float* __restrict__ p1w,
                                                   float* __restrict__ out) {
    const int branch = blockIdx.y;
    const int kz = blockIdx.z;
    const int tid = threadIdx.x;
    const int wid = tid >> 5, lane = tid & 31;

    // ---- CAM finalize on z=0 planes: 64 blocks x 49 = 3136 per branch ------
    if (kz == 0 && tid < 49) {
        int idx = branch * (2 * NDIM) + blockIdx.x * 49 + tid;
        float s = 0.f;
#pragma unroll
        for (int ch = 0; ch < 8; ch++) s += g_camp[ch * (NBR * 2 * NDIM) + idx];
        out[CAM_OFF + idx] = fmaxf(s, 0.f);
    }

    // ---- partial Linear: j = bx*8+wid, k in [kz*512, kz*512+512) -----------
    const int j = blockIdx.x * 8 + wid;
    const float* wp = p1w + (size_t)(branch * 512 + j) * 1024 + kz * 512;
    const float* pp = g_pooled + (branch * 1024 + kz * 512) * 32 + lane;

    float a0 = 0.f, a1 = 0.f, a2 = 0.f, a3 = 0.f;
#pragma unroll 8
    for (int t = 0; t < 512; t += 8) {
        float4 w0 = *(const float4*)(wp + t);
        float4 w1 = *(const float4*)(wp + t + 4);
        a0 = fmaf(w0.x, pp[(t + 0) * 32], a0);
        a1 = fmaf(w0.y, pp[(t + 1) * 32], a1);
        a2 = fmaf(w0.z, pp[(t + 2) * 32], a2);
        a3 = fmaf(w0.w, pp[(t + 3) * 32], a3);
        a0 = fmaf(w1.x, pp[(t + 4) * 32], a0);
        a1 = fmaf(w1.y, pp[(t + 5) * 32], a1);
        a2 = fmaf(w1.z, pp[(t + 6) * 32], a2);
        a3 = fmaf(w1.w, pp[(t + 7) * 32], a3);
    }
    g_hp[kz][(branch * 32 + lane) * 512 + j] = (a0 + a1) + (a2 + a3);
}

// ---------------------------------------------------------------------------
// Kernel 5: mlp2 — fuses h = relu(p0+p1+bias), Linear(512,2), softmax.
// grid 96 (one block per branch,image), 64 threads (warp per class).
// ---------------------------------------------------------------------------
__global__ __launch_bounds__(64) void mlp2_kernel(const float* __restrict__ p2w,
                                                  const float* __restrict__ p2b,
                                                  const float* __restrict__ p1b,
                                                  float* __restrict__ out) {
    const int branch = blockIdx.x / 32, b = blockIdx.x & 31;
    const int wid = threadIdx.x >> 5, lane = threadIdx.x & 31;
    const float* wv = p2w + branch * 1024 + wid * 512;
    const float* h0 = g_hp[0] + (branch * 32 + b) * 512;
    const float* h1 = g_hp[1] + (branch * 32 + b) * 512;
    const float* b1 = p1b + branch * 512;
    float s = 0.f;
#pragma unroll
    for (int t = 0; t < 16; t++) {
        int idx = t * 32 + lane;
        float hv = fmaxf(h0[idx] + h1[idx] + b1[idx], 0.f);
        s = fmaf(hv, wv[idx], s);
    }
#pragma unroll
    for (int off = 16; off; off >>= 1) s += __shfl_xor_sync(0xffffffffu, s, off);
    __shared__ float logit[2];
    if (lane == 0) logit[wid] = s + p2b[branch * 2 + wid];
    __syncthreads();
    if (threadIdx.x == 0) {
        float l0 = logit[0], l1 = logit[1];
        float mx = fmaxf(l0, l1);
        float e0 = expf(l0 - mx), e1 = expf(l1 - mx);
        out[RANK_OFF + b * 3 + branch] = e1 / (e0 + e1);
    }
}

// ---------------------------------------------------------------------------
// Launch: prep(1), gemm(2), postproc(3), mlp1(4 <- ncu slot), mlp2(5)
// ---------------------------------------------------------------------------
extern "C" void kernel_launch(void* const* d_in, const int* in_sizes, int n_in,
                              void* d_out, int out_size) {
    const float* x    = (const float*)d_in[0];
    const float* Wb   = (const float*)d_in[1];
    const float* bb   = (const float*)d_in[2];
    const float* p1w  = (const float*)d_in[3];
    const float* p1b  = (const float*)d_in[4];
    const float* p2w  = (const float*)d_in[5];
    const float* p2b  = (const float*)d_in[6];
    const float* clsw = (const float*)d_in[7];
    float* out = (float*)d_out;

    prep_kernel<<<A4_BLKS + B4_BLKS, 256>>>(Wb, x);

    cudaFuncSetAttribute(gemm_mma_kernel, cudaFuncAttributeMaxDynamicSharedMemorySize, SMEM_DYN);
    dim3 ggrid(NPAD / BN, MDIM / BM);   // (13, 48)
    gemm_mma_kernel<<<ggrid, 128, SMEM_DYN>>>(bb, out);

    postproc_kernel<<<dim3(NBR * BATCH, 8), 256>>>(out, clsw);
    mlp1_kernel<<<dim3(64, NBR, 2), 256>>>(p1w, out);
    mlp2_kernel<<<NBR * BATCH, 64>>>(p2w, p2b, p1b, out);
}